// round 11
// baseline (speedup 1.0000x reference)
#include <cuda_runtime.h>
#include <cuda_bf16.h>
#include <cstdint>

// ---------------------------------------------------------------------------
// Problem: B=32, NINP=128, NHID=256, W=512, K=2, NLAYERS=3
//
// Scratch:
//   g_xbuf[lv][b][c][p], p in [0,513): p=0 is left pad = hidden[lv][b][c][1],
//                        p=1+w is x_list[lv][b][c][w]. Row stride XW=520.
//   g_ig[l][b][w][o]: per-layer gate pre-activations (accumulated per conv j).
//   g_wT[jb][kk][o]: conv_w transposed (kk-major) for cp.async tile loads.
//
// Output (float32): [0,65536) x[:,:,:,-2:] (4,32,256,2)
//                   [65536,114688) nc[:,:,:,-2:] (3,32,256,2)
//                   [114688,163744) attns (3,32,511)
// ---------------------------------------------------------------------------

#define XW 520
#define NC_OFF   65536
#define ATTN_OFF 114688

// scan smem layout (bytes)
#define RW_OFF  0         // 131072: [32][256] uint4 (bf16x2 x4)
#define HR_OFF  131072    // 2048:   hr[2][256] float
#define GQ_OFF  133120    // 1024:   gq[256] float
#define RED_OFF 134144    // 32:     red[8]
#define MB_OFF  134176    // 16:     mbar[2]
#define SCAN_SMEM 134208

__device__ float g_xbuf[4][32][256][XW];      // ~68 MB
__device__ float g_ig[3][32][512][1024];      // ~201 MB
__device__ float g_wT[6][512][1024];          // ~12.6 MB

__device__ __forceinline__ float tanh_ap(float x) {
    float y; asm("tanh.approx.f32 %0, %1;" : "=f"(y) : "f"(x)); return y;
}
__device__ __forceinline__ float sigm_ap(float x) {
    return 0.5f * tanh_ap(0.5f * x) + 0.5f;
}
__device__ __forceinline__ uint32_t smem_u32(const void* p) {
    return (uint32_t)__cvta_generic_to_shared(p);
}
__device__ __forceinline__ uint32_t mapa_rank(uint32_t a, uint32_t r) {
    uint32_t d;
    asm("mapa.shared::cluster.u32 %0, %1, %2;" : "=r"(d) : "r"(a), "r"(r));
    return d;
}
__device__ __forceinline__ void st_cluster_f32(uint32_t a, float v) {
    asm volatile("st.shared::cluster.f32 [%0], %1;" :: "r"(a), "f"(v) : "memory");
}
__device__ __forceinline__ void mbar_init(uint32_t a, uint32_t cnt) {
    asm volatile("mbarrier.init.shared.b64 [%0], %1;" :: "r"(a), "r"(cnt) : "memory");
}
__device__ __forceinline__ void mbar_arrive_cluster(uint32_t a) {
    asm volatile("mbarrier.arrive.release.cluster.shared::cluster.b64 _, [%0];"
                 :: "r"(a) : "memory");
}
__device__ __forceinline__ void mbar_wait_acq(uint32_t a, uint32_t par) {
    uint32_t done;
    asm volatile(
        "{\n\t.reg .pred p;\n\t"
        "mbarrier.try_wait.parity.acquire.cluster.shared::cta.b64 p, [%1], %2;\n\t"
        "selp.b32 %0, 1, 0, p;\n\t}"
        : "=r"(done) : "r"(a), "r"(par) : "memory");
    if (!done) {
        asm volatile(
            "{\n\t.reg .pred P1;\n\t"
            "WL_%=:\n\t"
            "mbarrier.try_wait.parity.acquire.cluster.shared::cta.b64 P1, [%0], %1, 0x989680;\n\t"
            "@P1 bra.uni WD_%=;\n\t"
            "bra.uni WL_%=;\n\t"
            "WD_%=:\n\t}"
            :: "r"(a), "r"(par) : "memory");
    }
}
__device__ __forceinline__ void cluster_sync_() {
    asm volatile("barrier.cluster.arrive.aligned;" ::: "memory");
    asm volatile("barrier.cluster.wait.aligned;" ::: "memory");
}
__device__ __forceinline__ void cp16(void* dst, const void* src) {
    asm volatile("cp.async.cg.shared.global [%0], [%1], 16;"
                 :: "r"(smem_u32(dst)), "l"(src) : "memory");
}
__device__ __forceinline__ void cp4(void* dst, const void* src) {
    asm volatile("cp.async.ca.shared.global [%0], [%1], 4;"
                 :: "r"(smem_u32(dst)), "l"(src) : "memory");
}
__device__ __forceinline__ void cp_commit() {
    asm volatile("cp.async.commit_group;" ::: "memory");
}

// ------------------------- conv_w transpose --------------------------------
__global__ void transpose_w_kernel(const float* __restrict__ conv_w) {
    __shared__ float tile[32][33];
    int jb = blockIdx.z, o0 = blockIdx.y * 32, k0 = blockIdx.x * 32;
    int tx = threadIdx.x, ty = threadIdx.y;   // (32, 8)
#pragma unroll
    for (int i = 0; i < 32; i += 8)
        tile[ty + i][tx] = conv_w[((size_t)jb * 1024 + o0 + ty + i) * 512 + k0 + tx];
    __syncthreads();
#pragma unroll
    for (int i = 0; i < 32; i += 8)
        g_wT[jb][k0 + ty + i][o0 + tx] = tile[tx][ty + i];
}

// ------------------------- pad init ----------------------------------------
__global__ void init_pads_kernel(const float* __restrict__ hidden) {
    int idx = blockIdx.x * blockDim.x + threadIdx.x;   // 32768
    if (idx >= 4 * 32 * 256) return;
    int lv = idx >> 13;
    int b  = (idx >> 8) & 31;
    int c  = idx & 255;
    g_xbuf[lv][b][c][0] = hidden[((size_t)((lv * 32 + b) * 256 + c)) * 2 + 1];
}

// ------------------------- x0 tail copy to output --------------------------
__global__ void copy_x0_kernel(float* __restrict__ out) {
    int idx = blockIdx.x * blockDim.x + threadIdx.x;   // 16384
    if (idx >= 16384) return;
    int tt = idx & 1;
    int h  = (idx >> 1) & 255;
    int b  = idx >> 9;
    out[idx] = g_xbuf[0][b][h][511 + tt];
}

// ------------------------- embedding GEMM ----------------------------------
__global__ void __launch_bounds__(256, 2)
emb_gemm_kernel(const float* __restrict__ input,
                const float* __restrict__ emb_w,
                const float* __restrict__ emb_b) {
    __shared__ float As[16][132];
    __shared__ float Bs[16][136];
    const int o0 = blockIdx.x * 128, w0 = blockIdx.y * 128, b = blockIdx.z;
    const int tid = threadIdx.x, tx = tid & 15, ty = tid >> 4;

    float acc[8][8];
#pragma unroll
    for (int j = 0; j < 8; j++)
#pragma unroll
        for (int i = 0; i < 8; i++) acc[j][i] = 0.f;

    for (int k0 = 0; k0 < 128; k0 += 16) {
        __syncthreads();
        {
            int cg = tid & 3;
            int row = tid >> 2;
#pragma unroll
            for (int p = 0; p < 2; p++) {
                int r_ = row + p * 64;
                float4 v = *(const float4*)(emb_w + (size_t)(o0 + r_) * 128 + k0 + cg * 4);
                As[cg * 4 + 0][r_] = v.x; As[cg * 4 + 1][r_] = v.y;
                As[cg * 4 + 2][r_] = v.z; As[cg * 4 + 3][r_] = v.w;
            }
        }
        {
            for (int i = tid; i < 512; i += 256) {
                int r = i >> 5, q = i & 31;
                float4 v = *(const float4*)(input + (size_t)(b * 128 + k0 + r) * 512 + w0 + q * 4);
                Bs[r][q * 4 + 0] = v.x; Bs[r][q * 4 + 1] = v.y;
                Bs[r][q * 4 + 2] = v.z; Bs[r][q * 4 + 3] = v.w;
            }
        }
        __syncthreads();
#pragma unroll
        for (int k = 0; k < 16; k++) {
            float4 a0 = *(const float4*)&As[k][ty * 8];
            float4 a1 = *(const float4*)&As[k][ty * 8 + 4];
            float4 b0 = *(const float4*)&Bs[k][tx * 4];
            float4 b1 = *(const float4*)&Bs[k][64 + tx * 4];
            float av[8] = {a0.x, a0.y, a0.z, a0.w, a1.x, a1.y, a1.z, a1.w};
            float bv[8] = {b0.x, b0.y, b0.z, b0.w, b1.x, b1.y, b1.z, b1.w};
#pragma unroll
            for (int j = 0; j < 8; j++)
#pragma unroll
                for (int i = 0; i < 8; i++) acc[j][i] = fmaf(av[i], bv[j], acc[j][i]);
        }
    }
#pragma unroll
    for (int i = 0; i < 8; i++) {
        int o = o0 + ty * 8 + i;
        float bias = emb_b[o];
        float* dst = &g_xbuf[0][b][o][1 + w0];
#pragma unroll
        for (int j = 0; j < 4; j++) dst[tx * 4 + j] = acc[j][i] + bias;
#pragma unroll
        for (int j = 0; j < 4; j++) dst[64 + tx * 4 + j] = acc[4 + j][i] + bias;
    }
}

// ------------------------- conv contribution GEMM --------------------------
// One (layer, j) pass: g_ig[lay][b][w][o] (+)= conv_b[jb][o]
//        + sum_kk g_wT[jb][kk][o] * g_xbuf[jl][b][kk>>1][w + (kk&1)]
__global__ void __launch_bounds__(256, 2)
conv_gemm_kernel(int jb, int jl, int lay, int accum, const float* __restrict__ conv_b) {
    __shared__ float As[2][16][132];
    __shared__ float Bs[2][16][136];
    const int o0 = blockIdx.x * 128, w0 = blockIdx.y * 128, b = blockIdx.z;
    const int tid = threadIdx.x, tx = tid & 15, ty = tid >> 4;
    const int total = 32;

    float acc[8][8];
#pragma unroll
    for (int j = 0; j < 8; j++)
#pragma unroll
        for (int i = 0; i < 8; i++) acc[j][i] = 0.f;

    auto load_tile = [&](int buf, int kt) {
        int kk0 = kt << 4;
        const float* WT = &g_wT[jb][kk0][0];
#pragma unroll
        for (int s = 0; s < 2; s++) {
            int idx = tid + s * 256;
            int row = idx >> 5, c4 = idx & 31;
            cp16(&As[buf][row][c4 * 4], WT + (size_t)row * 1024 + o0 + c4 * 4);
        }
        {
            int row = tid >> 4;
            int colb = (tid & 15) * 8;
            int kkg = kk0 + row;
            const float* src = &g_xbuf[jl][b][kkg >> 1][w0 + (kkg & 1) + colb];
            if ((kkg & 1) == 0) {
                cp16(&Bs[buf][row][colb], src);
                cp16(&Bs[buf][row][colb + 4], src + 4);
            } else {
#pragma unroll
                for (int q = 0; q < 8; q++) cp4(&Bs[buf][row][colb + q], src + q);
            }
        }
    };

    load_tile(0, 0); cp_commit();
    load_tile(1, 1); cp_commit();

    for (int kt = 0; kt < total; kt++) {
        if (kt + 1 < total) asm volatile("cp.async.wait_group 1;" ::: "memory");
        else                asm volatile("cp.async.wait_group 0;" ::: "memory");
        __syncthreads();
        int buf = kt & 1;
#pragma unroll
        for (int k = 0; k < 16; k++) {
            float4 a0 = *(const float4*)&As[buf][k][ty * 8];
            float4 a1 = *(const float4*)&As[buf][k][ty * 8 + 4];
            float4 b0 = *(const float4*)&Bs[buf][k][tx * 4];
            float4 b1 = *(const float4*)&Bs[buf][k][64 + tx * 4];
            float av[8] = {a0.x, a0.y, a0.z, a0.w, a1.x, a1.y, a1.z, a1.w};
            float bv[8] = {b0.x, b0.y, b0.z, b0.w, b1.x, b1.y, b1.z, b1.w};
#pragma unroll
            for (int jw = 0; jw < 8; jw++)
#pragma unroll
                for (int io = 0; io < 8; io++) acc[jw][io] = fmaf(av[io], bv[jw], acc[jw][io]);
        }
        __syncthreads();
        if (kt + 2 < total) { load_tile(buf, kt + 2); cp_commit(); }
    }

    float bias[8];
#pragma unroll
    for (int i = 0; i < 8; i++) bias[i] = conv_b[jb * 1024 + o0 + ty * 8 + i];

#pragma unroll
    for (int jw = 0; jw < 8; jw++) {
        int wl = (jw < 4) ? (tx * 4 + jw) : (64 + tx * 4 + (jw - 4));
        float* dst = &g_ig[lay][b][w0 + wl][o0 + ty * 8];
        float4 o_ = make_float4(0.f, 0.f, 0.f, 0.f), o2 = o_;
        if (accum) { o_ = *(const float4*)dst; o2 = *(const float4*)(dst + 4); }
        float4 v0 = make_float4(o_.x + acc[jw][0] + bias[0], o_.y + acc[jw][1] + bias[1],
                                o_.z + acc[jw][2] + bias[2], o_.w + acc[jw][3] + bias[3]);
        float4 v1 = make_float4(o2.x + acc[jw][4] + bias[4], o2.y + acc[jw][5] + bias[5],
                                o2.z + acc[jw][6] + bias[6], o2.w + acc[jw][7] + bias[7]);
        *(float4*)dst = v0;
        *(float4*)(dst + 4) = v1;
    }
}

// ------------------------- LSTM scan (4-CTA cluster per batch) -------------
// CTA rank r owns h in [64r, 64r+64): weight rows {g*256 + 64r + hl}. The
// LSTM update is LOCAL; only the 64 hr values cross CTAs (double-buffered,
// one mbarrier per step). Attention scalar a is folded into the next step's
// matvec: gate = a_prev * dot(rw, hr_prev) + rb + ig.
__global__ void __launch_bounds__(256, 2) __cluster_dims__(4, 1, 1)
scan_kernel(int l,
            const float* __restrict__ hidden, const float* __restrict__ context,
            const float* __restrict__ rec_w, const float* __restrict__ rec_b,
            const float* __restrict__ attn_w, float* __restrict__ out) {
    extern __shared__ uint8_t sm8[];
    uint4* rw4   = (uint4*)(sm8 + RW_OFF);     // [32][256]
    float* hrbuf = (float*)(sm8 + HR_OFF);     // [2][256]
    float* gq    = (float*)(sm8 + GQ_OFF);     // [256]
    float* red   = (float*)(sm8 + RED_OFF);    // [8]

    const int t = threadIdx.x;
    const int b = blockIdx.x >> 2;
    uint32_t rank;
    asm("mov.u32 %0, %%cluster_ctarank;" : "=r"(rank));
    const int nl = l + 1;
    const int g_idx = t >> 6, hl = t & 63;
    const int G = g_idx * 256 + 64 * (int)rank + hl;   // my gate row

    const float* rwl = rec_w + (size_t)l * 1024 * 256;
#pragma unroll 4
    for (int q = 0; q < 32; q++) {
        const float* p = rwl + (size_t)G * 256 + q * 8;
        __nv_bfloat162 p0 = __floats2bfloat162_rn(p[0], p[1]);
        __nv_bfloat162 p1 = __floats2bfloat162_rn(p[2], p[3]);
        __nv_bfloat162 p2 = __floats2bfloat162_rn(p[4], p[5]);
        __nv_bfloat162 p3 = __floats2bfloat162_rn(p[6], p[7]);
        uint4 u;
        u.x = *(uint32_t*)&p0; u.y = *(uint32_t*)&p1;
        u.z = *(uint32_t*)&p2; u.w = *(uint32_t*)&p3;
        rw4[(q << 8) + t] = u;
    }
    hrbuf[256 + t] = hidden[((size_t)((nl * 32 + b) * 256 + t)) * 2 + 1];

    const int h_glob = 64 * (int)rank + hl;
    float cx = context[((size_t)((l * 32 + b) * 256 + h_glob)) * 2 + 1];
    float hr_prev = 0.f;

    const float rb_t = rec_b[l * 1024 + G];
    const float aw_t = attn_w[l * 256 + t];

    const uint32_t hr_base = smem_u32(sm8 + HR_OFF);
    const uint32_t mb_base = smem_u32(sm8 + MB_OFF);
    uint32_t hr_peer[4], mb_peer[4];
#pragma unroll
    for (int r = 0; r < 4; r++) {
        hr_peer[r] = mapa_rank(hr_base, r);
        mb_peer[r] = mapa_rank(mb_base, r);
    }
    if (t == 0) { mbar_init(mb_base, 256); mbar_init(mb_base + 8, 256); }
    __syncthreads();
    cluster_sync_();

    const float* igb = &g_ig[l][b][0][0];
    float* gx_next = &g_xbuf[nl][b][0][0];
    const int lane = t & 31, warp = t >> 5;

    for (int w = 0; w < 512; w++) {
        const int jprev = (w + 1) & 1;
        if (w > 0) mbar_wait_acq(mb_base + (uint32_t)(jprev << 3),
                                 (uint32_t)(((w - 1) >> 1) & 1));

        const float* hrp = hrbuf + (jprev << 8);

        float p = hrp[t] * aw_t;
#pragma unroll
        for (int o_ = 16; o_ > 0; o_ >>= 1) p += __shfl_xor_sync(0xffffffffu, p, o_);
        if (lane == 0) red[warp] = p;
        __syncthreads();
        float s = 0.f;
#pragma unroll
        for (int q = 0; q < 8; q++) s += red[q];
        float a_prev = (w > 0) ? sigm_ap(s) : 1.f;

        float igv = igb[(size_t)w * 1024 + G];

        float a0 = 0.f, a1 = 0.f, a2 = 0.f, a3 = 0.f;
        const float4* hx4 = (const float4*)hrp;
#pragma unroll
        for (int q = 0; q < 32; q++) {
            uint4 u = rw4[(q << 8) + t];
            float4 ha = hx4[2 * q];
            float4 hb = hx4[2 * q + 1];
            a0 = fmaf(__uint_as_float(u.x << 16), ha.x, a0);
            a1 = fmaf(__uint_as_float(u.x),       ha.y, a1);
            a2 = fmaf(__uint_as_float(u.y << 16), ha.z, a2);
            a3 = fmaf(__uint_as_float(u.y),       ha.w, a3);
            a0 = fmaf(__uint_as_float(u.z << 16), hb.x, a0);
            a1 = fmaf(__uint_as_float(u.z),       hb.y, a1);
            a2 = fmaf(__uint_as_float(u.w << 16), hb.z, a2);
            a3 = fmaf(__uint_as_float(u.w),       hb.w, a3);
        }
        gq[t] = a_prev * (((a0 + a1) + (a2 + a3))) + rb_t + igv;
        __syncthreads();

        if (t < 64) {
            if (w > 0) {
                float hxprev = hr_prev * a_prev;
                gx_next[(size_t)h_glob * XW + w] = hxprev;
                if (w == 511)
                    out[((size_t)((nl * 32 + b) * 256 + h_glob)) * 2 + 0] = hxprev;
            }
            float gi = gq[t], gf = gq[64 + t], gc = gq[128 + t], go = gq[192 + t];
            cx = sigm_ap(gf) * cx + sigm_ap(gi) * tanh_ap(gc);
            float hr = sigm_ap(go) * tanh_ap(cx);
            if (w >= 510)
                out[NC_OFF + ((size_t)((l * 32 + b) * 256 + h_glob)) * 2 + (w - 510)] = cx;
            if (w == 511) {
                out[((size_t)((nl * 32 + b) * 256 + h_glob)) * 2 + 1] = hr;
                gx_next[(size_t)h_glob * XW + 512] = hr;
            } else {
                uint32_t soff = (uint32_t)((((w & 1) << 8) + h_glob) << 2);
#pragma unroll
                for (int r = 0; r < 4; r++) st_cluster_f32(hr_peer[r] + soff, hr);
#pragma unroll
                for (int r = 0; r < 4; r++)
                    mbar_arrive_cluster(mb_peer[r] + (uint32_t)((w & 1) << 3));
            }
            hr_prev = hr;
        }
        if (rank == 0 && t == 0 && w > 0)
            out[ATTN_OFF + (size_t)(l * 32 + b) * 511 + (w - 1)] = a_prev;
    }
    cluster_sync_();
}

// ------------------------- stream/event context (pre-main init) ------------
__global__ void noop_kernel() {}

struct StreamCtx {
    cudaStream_t s1 = 0, s2 = 0;
    cudaEvent_t e0 = 0, ex1 = 0, ex2 = 0, c1 = 0, c2 = 0;
    bool ok = false;
    StreamCtx() {
        int lo = 0, hi = 0;
        cudaDeviceGetStreamPriorityRange(&lo, &hi);   // lo = least priority
        if (cudaStreamCreateWithPriority(&s1, cudaStreamNonBlocking, lo) != cudaSuccess) return;
        if (cudaStreamCreateWithPriority(&s2, cudaStreamNonBlocking, lo) != cudaSuccess) return;
        cudaEventCreateWithFlags(&e0,  cudaEventDisableTiming);
        cudaEventCreateWithFlags(&ex1, cudaEventDisableTiming);
        cudaEventCreateWithFlags(&ex2, cudaEventDisableTiming);
        cudaEventCreateWithFlags(&c1,  cudaEventDisableTiming);
        cudaEventCreateWithFlags(&c2,  cudaEventDisableTiming);
        // warm up stream resources pre-checkpoint
        noop_kernel<<<1, 32, 0, s1>>>();
        noop_kernel<<<1, 32, 0, s2>>>();
        cudaEventRecord(e0, s1);
        cudaEventRecord(ex1, s2);
        cudaDeviceSynchronize();
        ok = true;
    }
};
static StreamCtx g_sc;

// ---------------------------------------------------------------------------
extern "C" void kernel_launch(void* const* d_in, const int* in_sizes, int n_in,
                              void* d_out, int out_size) {
    const float* input   = (const float*)d_in[0];
    const float* hidden  = (const float*)d_in[1];
    const float* context = (const float*)d_in[2];
    const float* emb_w   = (const float*)d_in[3];
    const float* emb_b   = (const float*)d_in[4];
    const float* conv_w  = (const float*)d_in[5];
    const float* conv_b  = (const float*)d_in[6];
    const float* rec_w   = (const float*)d_in[7];
    const float* rec_b   = (const float*)d_in[8];
    const float* attn_w  = (const float*)d_in[9];
    float* out = (float*)d_out;

    cudaFuncSetAttribute(scan_kernel, cudaFuncAttributeMaxDynamicSharedMemorySize, SCAN_SMEM);

    const dim3 cgrid(8, 4, 32);

    transpose_w_kernel<<<dim3(16, 32, 6), dim3(32, 8)>>>(conv_w);
    init_pads_kernel<<<128, 256>>>(hidden);
    emb_gemm_kernel<<<dim3(2, 4, 32), 256>>>(input, emb_w, emb_b);
    copy_x0_kernel<<<64, 256>>>(out);

    if (g_sc.ok) {
        cudaEventRecord(g_sc.e0, 0);
        // layer 0 j=0 on main (critical path)
        conv_gemm_kernel<<<cgrid, 256>>>(0, 0, 0, 0, conv_b);
        // independent contributions fork off
        cudaStreamWaitEvent(g_sc.s1, g_sc.e0, 0);
        conv_gemm_kernel<<<cgrid, 256, 0, g_sc.s1>>>(1, 0, 1, 0, conv_b);   // (l=1,j=0)
        cudaStreamWaitEvent(g_sc.s2, g_sc.e0, 0);
        conv_gemm_kernel<<<cgrid, 256, 0, g_sc.s2>>>(3, 0, 2, 0, conv_b);   // (l=2,j=0)

        scan_kernel<<<128, 256, SCAN_SMEM>>>(0, hidden, context, rec_w, rec_b, attn_w, out);
        cudaEventRecord(g_sc.ex1, 0);

        cudaStreamWaitEvent(g_sc.s1, g_sc.ex1, 0);
        conv_gemm_kernel<<<cgrid, 256, 0, g_sc.s1>>>(2, 1, 1, 1, conv_b);   // (l=1,j=1)
        cudaEventRecord(g_sc.c1, g_sc.s1);
        cudaStreamWaitEvent(g_sc.s2, g_sc.ex1, 0);
        conv_gemm_kernel<<<cgrid, 256, 0, g_sc.s2>>>(4, 1, 2, 1, conv_b);   // (l=2,j=1)

        cudaStreamWaitEvent(0, g_sc.c1, 0);
        scan_kernel<<<128, 256, SCAN_SMEM>>>(1, hidden, context, rec_w, rec_b, attn_w, out);
        cudaEventRecord(g_sc.ex2, 0);

        cudaStreamWaitEvent(g_sc.s2, g_sc.ex2, 0);
        conv_gemm_kernel<<<cgrid, 256, 0, g_sc.s2>>>(5, 2, 2, 1, conv_b);   // (l=2,j=2)
        cudaEventRecord(g_sc.c2, g_sc.s2);

        cudaStreamWaitEvent(0, g_sc.c2, 0);
        scan_kernel<<<128, 256, SCAN_SMEM>>>(2, hidden, context, rec_w, rec_b, attn_w, out);
    } else {
        // serial fallback
        for (int l = 0; l < 3; l++) {
            int off = (l * (l + 1)) >> 1;
            for (int j = 0; j <= l; j++)
                conv_gemm_kernel<<<cgrid, 256>>>(off + j, j, l, j > 0, conv_b);
            scan_kernel<<<128, 256, SCAN_SMEM>>>(l, hidden, context, rec_w, rec_b, attn_w, out);
        }
    }
}

// round 12
// speedup vs baseline: 1.2298x; 1.2298x over previous
#include <cuda_runtime.h>
#include <cuda_bf16.h>
#include <cstdint>

// ---------------------------------------------------------------------------
// Problem: B=32, NINP=128, NHID=256, W=512, K=2, NLAYERS=3
//
// Scratch:
//   g_xbuf[lv][b][c][p], p in [0,513): p=0 is left pad = hidden[lv][b][c][1],
//                        p=1+w is x_list[lv][b][c][w]. Row stride XW=520.
//                        Values stored PRE-ROUNDED to tf32 (conv-only consumer).
//   g_ig[l][b][w][o]: per-layer gate pre-activations (accumulated per conv j).
//   g_wT[jb][kk][o]: conv_w transposed (kk-major), tf32-rounded.
//
// Output (float32): [0,65536) x[:,:,:,-2:] (4,32,256,2)
//                   [65536,114688) nc[:,:,:,-2:] (3,32,256,2)
//                   [114688,163744) attns (3,32,511)
// ---------------------------------------------------------------------------

#define XW 520
#define NC_OFF   65536
#define ATTN_OFF 114688

// scan smem layout (bytes)
#define RW_OFF  0         // 131072: [32][256] uint4 (bf16x2 x4)
#define HR_OFF  131072    // 2048:   hr[2][256] float
#define GQ_OFF  133120    // 1024:   gq[256] float
#define RED_OFF 134144    // 32:     red[8]
#define MB_OFF  134176    // 16:     mbar[2]
#define SCAN_SMEM 134208

__device__ float g_xbuf[4][32][256][XW];      // ~68 MB
__device__ float g_ig[3][32][512][1024];      // ~201 MB
__device__ float g_wT[6][512][1024];          // ~12.6 MB

__device__ __forceinline__ float tanh_ap(float x) {
    float y; asm("tanh.approx.f32 %0, %1;" : "=f"(y) : "f"(x)); return y;
}
__device__ __forceinline__ float sigm_ap(float x) {
    return 0.5f * tanh_ap(0.5f * x) + 0.5f;
}
__device__ __forceinline__ float to_tf32(float x) {
    float r; asm("cvt.rna.tf32.f32 %0, %1;" : "=f"(r) : "f"(x)); return r;
}
__device__ __forceinline__ uint32_t smem_u32(const void* p) {
    return (uint32_t)__cvta_generic_to_shared(p);
}
__device__ __forceinline__ uint32_t mapa_rank(uint32_t a, uint32_t r) {
    uint32_t d;
    asm("mapa.shared::cluster.u32 %0, %1, %2;" : "=r"(d) : "r"(a), "r"(r));
    return d;
}
__device__ __forceinline__ void st_cluster_f32(uint32_t a, float v) {
    asm volatile("st.shared::cluster.f32 [%0], %1;" :: "r"(a), "f"(v) : "memory");
}
__device__ __forceinline__ void mbar_init(uint32_t a, uint32_t cnt) {
    asm volatile("mbarrier.init.shared.b64 [%0], %1;" :: "r"(a), "r"(cnt) : "memory");
}
__device__ __forceinline__ void mbar_arrive_cluster(uint32_t a) {
    asm volatile("mbarrier.arrive.release.cluster.shared::cluster.b64 _, [%0];"
                 :: "r"(a) : "memory");
}
__device__ __forceinline__ void mbar_wait_acq(uint32_t a, uint32_t par) {
    uint32_t done;
    asm volatile(
        "{\n\t.reg .pred p;\n\t"
        "mbarrier.try_wait.parity.acquire.cluster.shared::cta.b64 p, [%1], %2;\n\t"
        "selp.b32 %0, 1, 0, p;\n\t}"
        : "=r"(done) : "r"(a), "r"(par) : "memory");
    if (!done) {
        asm volatile(
            "{\n\t.reg .pred P1;\n\t"
            "WL_%=:\n\t"
            "mbarrier.try_wait.parity.acquire.cluster.shared::cta.b64 P1, [%0], %1, 0x989680;\n\t"
            "@P1 bra.uni WD_%=;\n\t"
            "bra.uni WL_%=;\n\t"
            "WD_%=:\n\t}"
            :: "r"(a), "r"(par) : "memory");
    }
}
__device__ __forceinline__ void cluster_sync_() {
    asm volatile("barrier.cluster.arrive.aligned;" ::: "memory");
    asm volatile("barrier.cluster.wait.aligned;" ::: "memory");
}
__device__ __forceinline__ void cp16(void* dst, const void* src) {
    asm volatile("cp.async.cg.shared.global [%0], [%1], 16;"
                 :: "r"(smem_u32(dst)), "l"(src) : "memory");
}
__device__ __forceinline__ void cp4(void* dst, const void* src) {
    asm volatile("cp.async.ca.shared.global [%0], [%1], 4;"
                 :: "r"(smem_u32(dst)), "l"(src) : "memory");
}
__device__ __forceinline__ void cp_commit() {
    asm volatile("cp.async.commit_group;" ::: "memory");
}
__device__ __forceinline__ void mma_tf32(float* d, const uint32_t* a,
                                         uint32_t b0, uint32_t b1) {
    asm volatile(
        "mma.sync.aligned.m16n8k8.row.col.f32.tf32.tf32.f32 "
        "{%0,%1,%2,%3}, {%4,%5,%6,%7}, {%8,%9}, {%0,%1,%2,%3};"
        : "+f"(d[0]), "+f"(d[1]), "+f"(d[2]), "+f"(d[3])
        : "r"(a[0]), "r"(a[1]), "r"(a[2]), "r"(a[3]), "r"(b0), "r"(b1));
}

// ------------------------- conv_w transpose (tf32-rounded) ------------------
__global__ void transpose_w_kernel(const float* __restrict__ conv_w) {
    __shared__ float tile[32][33];
    int jb = blockIdx.z, o0 = blockIdx.y * 32, k0 = blockIdx.x * 32;
    int tx = threadIdx.x, ty = threadIdx.y;   // (32, 8)
#pragma unroll
    for (int i = 0; i < 32; i += 8)
        tile[ty + i][tx] = conv_w[((size_t)jb * 1024 + o0 + ty + i) * 512 + k0 + tx];
    __syncthreads();
#pragma unroll
    for (int i = 0; i < 32; i += 8)
        g_wT[jb][k0 + ty + i][o0 + tx] = to_tf32(tile[tx][ty + i]);
}

// ------------------------- pad init (tf32-rounded) --------------------------
__global__ void init_pads_kernel(const float* __restrict__ hidden) {
    int idx = blockIdx.x * blockDim.x + threadIdx.x;   // 32768
    if (idx >= 4 * 32 * 256) return;
    int lv = idx >> 13;
    int b  = (idx >> 8) & 31;
    int c  = idx & 255;
    g_xbuf[lv][b][c][0] = to_tf32(hidden[((size_t)((lv * 32 + b) * 256 + c)) * 2 + 1]);
}

// ------------------------- embedding GEMM ----------------------------------
// Writes tf32-rounded x0 to g_xbuf; exact fp32 tail (w=510,511) to out.
__global__ void __launch_bounds__(256, 2)
emb_gemm_kernel(const float* __restrict__ input,
                const float* __restrict__ emb_w,
                const float* __restrict__ emb_b,
                float* __restrict__ out) {
    __shared__ float As[16][132];
    __shared__ float Bs[16][136];
    const int o0 = blockIdx.x * 128, w0 = blockIdx.y * 128, b = blockIdx.z;
    const int tid = threadIdx.x, tx = tid & 15, ty = tid >> 4;

    float acc[8][8];
#pragma unroll
    for (int j = 0; j < 8; j++)
#pragma unroll
        for (int i = 0; i < 8; i++) acc[j][i] = 0.f;

    for (int k0 = 0; k0 < 128; k0 += 16) {
        __syncthreads();
        {
            int cg = tid & 3;
            int row = tid >> 2;
#pragma unroll
            for (int p = 0; p < 2; p++) {
                int r_ = row + p * 64;
                float4 v = *(const float4*)(emb_w + (size_t)(o0 + r_) * 128 + k0 + cg * 4);
                As[cg * 4 + 0][r_] = v.x; As[cg * 4 + 1][r_] = v.y;
                As[cg * 4 + 2][r_] = v.z; As[cg * 4 + 3][r_] = v.w;
            }
        }
        {
            for (int i = tid; i < 512; i += 256) {
                int r = i >> 5, q = i & 31;
                float4 v = *(const float4*)(input + (size_t)(b * 128 + k0 + r) * 512 + w0 + q * 4);
                Bs[r][q * 4 + 0] = v.x; Bs[r][q * 4 + 1] = v.y;
                Bs[r][q * 4 + 2] = v.z; Bs[r][q * 4 + 3] = v.w;
            }
        }
        __syncthreads();
#pragma unroll
        for (int k = 0; k < 16; k++) {
            float4 a0 = *(const float4*)&As[k][ty * 8];
            float4 a1 = *(const float4*)&As[k][ty * 8 + 4];
            float4 b0 = *(const float4*)&Bs[k][tx * 4];
            float4 b1 = *(const float4*)&Bs[k][64 + tx * 4];
            float av[8] = {a0.x, a0.y, a0.z, a0.w, a1.x, a1.y, a1.z, a1.w};
            float bv[8] = {b0.x, b0.y, b0.z, b0.w, b1.x, b1.y, b1.z, b1.w};
#pragma unroll
            for (int j = 0; j < 8; j++)
#pragma unroll
                for (int i = 0; i < 8; i++) acc[j][i] = fmaf(av[i], bv[j], acc[j][i]);
        }
    }
#pragma unroll
    for (int i = 0; i < 8; i++) {
        int o = o0 + ty * 8 + i;
        float bias = emb_b[o];
        float* dst = &g_xbuf[0][b][o][1 + w0];
#pragma unroll
        for (int j = 0; j < 8; j++) {
            int wl = (j < 4) ? (tx * 4 + j) : (64 + tx * 4 + (j - 4));
            float v = acc[j][i] + bias;
            dst[wl] = to_tf32(v);
            int wg = w0 + wl;
            if (wg >= 510)
                out[((size_t)(b * 256 + o)) * 2 + (wg - 510)] = v;   // exact x0 tail
        }
    }
}

// ------------------------- conv contribution GEMM (tf32 tensor cores) ------
// g_ig[lay][b][w][o] (+)= conv_b[jb][o]
//        + sum_kk g_wT[jb][kk][o] * g_xbuf[jl][b][kk>>1][w + (kk&1)]
// mma m16n8k8: m = w, n = o. Warp grid 2(w) x 4(o); warp tile 64w x 32o.
__global__ void __launch_bounds__(256, 2)
conv_mma_kernel(int jb, int jl, int lay, int accum, const float* __restrict__ conv_b) {
    __shared__ float As[2][16][136];   // weights: [kk][o]
    __shared__ float Bs[2][16][136];   // x:       [kk][w]
    const int o0 = blockIdx.x * 128, w0 = blockIdx.y * 128, b = blockIdx.z;
    const int tid = threadIdx.x;
    const int wid = tid >> 5, lane = tid & 31;
    const int warp_m = wid >> 2;       // w half: 0..1
    const int warp_n = wid & 3;        // o quarter: 0..3
    const int lr = lane >> 2, lc = lane & 3;
    const int total = 32;

    float acc[4][4][4];                // [mt][nt][frag]
#pragma unroll
    for (int mt = 0; mt < 4; mt++)
#pragma unroll
        for (int nt = 0; nt < 4; nt++)
#pragma unroll
            for (int f = 0; f < 4; f++) acc[mt][nt][f] = 0.f;

    auto load_tile = [&](int buf, int kt) {
        int kk0 = kt << 4;
        const float* WT = &g_wT[jb][kk0][0];
#pragma unroll
        for (int s = 0; s < 2; s++) {
            int idx = tid + s * 256;
            int row = idx >> 5, c4 = idx & 31;
            cp16(&As[buf][row][c4 * 4], WT + (size_t)row * 1024 + o0 + c4 * 4);
        }
        {
            int row = tid >> 4;
            int colb = (tid & 15) * 8;
            int kkg = kk0 + row;
            const float* src = &g_xbuf[jl][b][kkg >> 1][w0 + (kkg & 1) + colb];
            if ((kkg & 1) == 0) {
                cp16(&Bs[buf][row][colb], src);
                cp16(&Bs[buf][row][colb + 4], src + 4);
            } else {
#pragma unroll
                for (int q = 0; q < 8; q++) cp4(&Bs[buf][row][colb + q], src + q);
            }
        }
    };

    load_tile(0, 0); cp_commit();
    load_tile(1, 1); cp_commit();

    for (int kt = 0; kt < total; kt++) {
        if (kt + 1 < total) asm volatile("cp.async.wait_group 1;" ::: "memory");
        else                asm volatile("cp.async.wait_group 0;" ::: "memory");
        __syncthreads();
        int buf = kt & 1;
        const float (*Aw)[136] = As[buf];
        const float (*Bx)[136] = Bs[buf];
#pragma unroll
        for (int ks = 0; ks < 16; ks += 8) {
            uint32_t af[4][4];
#pragma unroll
            for (int mt = 0; mt < 4; mt++) {
                int wl = warp_m * 64 + mt * 16 + lr;
                af[mt][0] = __float_as_uint(Bx[ks + lc][wl]);
                af[mt][1] = __float_as_uint(Bx[ks + lc][wl + 8]);
                af[mt][2] = __float_as_uint(Bx[ks + 4 + lc][wl]);
                af[mt][3] = __float_as_uint(Bx[ks + 4 + lc][wl + 8]);
            }
#pragma unroll
            for (int nt = 0; nt < 4; nt++) {
                int ol = warp_n * 32 + nt * 8 + lr;
                uint32_t b0 = __float_as_uint(Aw[ks + lc][ol]);
                uint32_t b1 = __float_as_uint(Aw[ks + 4 + lc][ol]);
#pragma unroll
                for (int mt = 0; mt < 4; mt++)
                    mma_tf32(acc[mt][nt], af[mt], b0, b1);
            }
        }
        __syncthreads();
        if (kt + 2 < total) { load_tile(buf, kt + 2); cp_commit(); }
    }

    // epilogue: D[w][o] (+bias, + old if accum) -> g_ig[lay][b][w][o]
#pragma unroll
    for (int mt = 0; mt < 4; mt++) {
        int wg = w0 + warp_m * 64 + mt * 16 + lr;
#pragma unroll
        for (int nt = 0; nt < 4; nt++) {
            int og = o0 + warp_n * 32 + nt * 8 + 2 * lc;
            float bi0 = conv_b[jb * 1024 + og];
            float bi1 = conv_b[jb * 1024 + og + 1];
            float* d0 = &g_ig[lay][b][wg][og];
            float* d1 = &g_ig[lay][b][wg + 8][og];
            float2 p0 = accum ? *(float2*)d0 : make_float2(0.f, 0.f);
            float2 p1 = accum ? *(float2*)d1 : make_float2(0.f, 0.f);
            float2 v0 = make_float2(p0.x + acc[mt][nt][0] + bi0,
                                    p0.y + acc[mt][nt][1] + bi1);
            float2 v1 = make_float2(p1.x + acc[mt][nt][2] + bi0,
                                    p1.y + acc[mt][nt][3] + bi1);
            *(float2*)d0 = v0;
            *(float2*)d1 = v1;
        }
    }
}

// ------------------------- LSTM scan (4-CTA cluster per batch) -------------
// CTA rank r owns h in [64r, 64r+64): weight rows {g*256 + 64r + hl}. The
// LSTM update is LOCAL; only the 64 hr values cross CTAs (double-buffered,
// one mbarrier per step). Attention scalar a is folded into the next step's
// matvec: gate = a_prev * dot(rw, hr_prev) + rb + ig.
__global__ void __launch_bounds__(256, 2) __cluster_dims__(4, 1, 1)
scan_kernel(int l,
            const float* __restrict__ hidden, const float* __restrict__ context,
            const float* __restrict__ rec_w, const float* __restrict__ rec_b,
            const float* __restrict__ attn_w, float* __restrict__ out) {
    extern __shared__ uint8_t sm8[];
    uint4* rw4   = (uint4*)(sm8 + RW_OFF);     // [32][256]
    float* hrbuf = (float*)(sm8 + HR_OFF);     // [2][256]
    float* gq    = (float*)(sm8 + GQ_OFF);     // [256]
    float* red   = (float*)(sm8 + RED_OFF);    // [8]

    const int t = threadIdx.x;
    const int b = blockIdx.x >> 2;
    uint32_t rank;
    asm("mov.u32 %0, %%cluster_ctarank;" : "=r"(rank));
    const int nl = l + 1;
    const int g_idx = t >> 6, hl = t & 63;
    const int G = g_idx * 256 + 64 * (int)rank + hl;   // my gate row

    const float* rwl = rec_w + (size_t)l * 1024 * 256;
#pragma unroll 4
    for (int q = 0; q < 32; q++) {
        const float* p = rwl + (size_t)G * 256 + q * 8;
        __nv_bfloat162 p0 = __floats2bfloat162_rn(p[0], p[1]);
        __nv_bfloat162 p1 = __floats2bfloat162_rn(p[2], p[3]);
        __nv_bfloat162 p2 = __floats2bfloat162_rn(p[4], p[5]);
        __nv_bfloat162 p3 = __floats2bfloat162_rn(p[6], p[7]);
        uint4 u;
        u.x = *(uint32_t*)&p0; u.y = *(uint32_t*)&p1;
        u.z = *(uint32_t*)&p2; u.w = *(uint32_t*)&p3;
        rw4[(q << 8) + t] = u;
    }
    hrbuf[256 + t] = hidden[((size_t)((nl * 32 + b) * 256 + t)) * 2 + 1];

    const int h_glob = 64 * (int)rank + hl;
    float cx = context[((size_t)((l * 32 + b) * 256 + h_glob)) * 2 + 1];
    float hr_prev = 0.f;

    const float rb_t = rec_b[l * 1024 + G];
    const float aw_t = attn_w[l * 256 + t];

    const uint32_t hr_base = smem_u32(sm8 + HR_OFF);
    const uint32_t mb_base = smem_u32(sm8 + MB_OFF);
    uint32_t hr_peer[4], mb_peer[4];
#pragma unroll
    for (int r = 0; r < 4; r++) {
        hr_peer[r] = mapa_rank(hr_base, r);
        mb_peer[r] = mapa_rank(mb_base, r);
    }
    if (t == 0) { mbar_init(mb_base, 256); mbar_init(mb_base + 8, 256); }
    __syncthreads();
    cluster_sync_();

    const float* igb = &g_ig[l][b][0][0];
    float* gx_next = &g_xbuf[nl][b][0][0];
    const int lane = t & 31, warp = t >> 5;

    for (int w = 0; w < 512; w++) {
        const int jprev = (w + 1) & 1;
        if (w > 0) mbar_wait_acq(mb_base + (uint32_t)(jprev << 3),
                                 (uint32_t)(((w - 1) >> 1) & 1));

        const float* hrp = hrbuf + (jprev << 8);

        float p = hrp[t] * aw_t;
#pragma unroll
        for (int o_ = 16; o_ > 0; o_ >>= 1) p += __shfl_xor_sync(0xffffffffu, p, o_);
        if (lane == 0) red[warp] = p;
        __syncthreads();
        float s = 0.f;
#pragma unroll
        for (int q = 0; q < 8; q++) s += red[q];
        float a_prev = (w > 0) ? sigm_ap(s) : 1.f;

        float igv = igb[(size_t)w * 1024 + G];

        float a0 = 0.f, a1 = 0.f, a2 = 0.f, a3 = 0.f;
        const float4* hx4 = (const float4*)hrp;
#pragma unroll
        for (int q = 0; q < 32; q++) {
            uint4 u = rw4[(q << 8) + t];
            float4 ha = hx4[2 * q];
            float4 hb = hx4[2 * q + 1];
            a0 = fmaf(__uint_as_float(u.x << 16), ha.x, a0);
            a1 = fmaf(__uint_as_float(u.x),       ha.y, a1);
            a2 = fmaf(__uint_as_float(u.y << 16), ha.z, a2);
            a3 = fmaf(__uint_as_float(u.y),       ha.w, a3);
            a0 = fmaf(__uint_as_float(u.z << 16), hb.x, a0);
            a1 = fmaf(__uint_as_float(u.z),       hb.y, a1);
            a2 = fmaf(__uint_as_float(u.w << 16), hb.z, a2);
            a3 = fmaf(__uint_as_float(u.w),       hb.w, a3);
        }
        gq[t] = a_prev * (((a0 + a1) + (a2 + a3))) + rb_t + igv;
        __syncthreads();

        if (t < 64) {
            if (w > 0) {
                float hxprev = hr_prev * a_prev;
                gx_next[(size_t)h_glob * XW + w] = to_tf32(hxprev);
                if (w == 511)
                    out[((size_t)((nl * 32 + b) * 256 + h_glob)) * 2 + 0] = hxprev;
            }
            float gi = gq[t], gf = gq[64 + t], gc = gq[128 + t], go = gq[192 + t];
            cx = sigm_ap(gf) * cx + sigm_ap(gi) * tanh_ap(gc);
            float hr = sigm_ap(go) * tanh_ap(cx);
            if (w >= 510)
                out[NC_OFF + ((size_t)((l * 32 + b) * 256 + h_glob)) * 2 + (w - 510)] = cx;
            if (w == 511) {
                out[((size_t)((nl * 32 + b) * 256 + h_glob)) * 2 + 1] = hr;
                gx_next[(size_t)h_glob * XW + 512] = to_tf32(hr);
            } else {
                uint32_t soff = (uint32_t)((((w & 1) << 8) + h_glob) << 2);
#pragma unroll
                for (int r = 0; r < 4; r++) st_cluster_f32(hr_peer[r] + soff, hr);
#pragma unroll
                for (int r = 0; r < 4; r++)
                    mbar_arrive_cluster(mb_peer[r] + (uint32_t)((w & 1) << 3));
            }
            hr_prev = hr;
        }
        if (rank == 0 && t == 0 && w > 0)
            out[ATTN_OFF + (size_t)(l * 32 + b) * 511 + (w - 1)] = a_prev;
    }
    cluster_sync_();
}

// ---------------------------------------------------------------------------
extern "C" void kernel_launch(void* const* d_in, const int* in_sizes, int n_in,
                              void* d_out, int out_size) {
    const float* input   = (const float*)d_in[0];
    const float* hidden  = (const float*)d_in[1];
    const float* context = (const float*)d_in[2];
    const float* emb_w   = (const float*)d_in[3];
    const float* emb_b   = (const float*)d_in[4];
    const float* conv_w  = (const float*)d_in[5];
    const float* conv_b  = (const float*)d_in[6];
    const float* rec_w   = (const float*)d_in[7];
    const float* rec_b   = (const float*)d_in[8];
    const float* attn_w  = (const float*)d_in[9];
    float* out = (float*)d_out;

    cudaFuncSetAttribute(scan_kernel, cudaFuncAttributeMaxDynamicSharedMemorySize, SCAN_SMEM);

    const dim3 cgrid(8, 4, 32);

    transpose_w_kernel<<<dim3(16, 32, 6), dim3(32, 8)>>>(conv_w);
    init_pads_kernel<<<128, 256>>>(hidden);
    emb_gemm_kernel<<<dim3(2, 4, 32), 256>>>(input, emb_w, emb_b, out);

    for (int l = 0; l < 3; l++) {
        int off = (l * (l + 1)) >> 1;
        for (int j = 0; j <= l; j++)
            conv_mma_kernel<<<cgrid, 256>>>(off + j, j, l, j > 0, conv_b);
        scan_kernel<<<128, 256, SCAN_SMEM>>>(l, hidden, context, rec_w, rec_b, attn_w, out);
    }
}

// round 14
// speedup vs baseline: 1.5250x; 1.2400x over previous
#include <cuda_runtime.h>
#include <cuda_bf16.h>
#include <cstdint>

// ---------------------------------------------------------------------------
// Problem: B=32, NINP=128, NHID=256, W=512, K=2, NLAYERS=3
//
// Scratch:
//   g_xbuf[lv][b][c][p], p in [0,513): p=0 is left pad = hidden[lv][b][c][1],
//                        p=1+w is x_list[lv][b][c][w]. Row stride XW=520.
//                        Values stored PRE-ROUNDED to tf32 (conv-only consumer).
//   g_ig[l][b][w][o]: per-layer gate pre-activations (accumulated per conv j).
//   g_wT[jb][kk][o]: conv_w transposed (kk-major), tf32-rounded.
//
// Output (float32): [0,65536) x[:,:,:,-2:] (4,32,256,2)
//                   [65536,114688) nc[:,:,:,-2:] (3,32,256,2)
//                   [114688,163744) attns (3,32,511)
// ---------------------------------------------------------------------------

#define XW 520
#define NC_OFF   65536
#define ATTN_OFF 114688

__device__ float g_xbuf[4][32][256][XW];      // ~68 MB
__device__ float g_ig[3][32][512][1024];      // ~201 MB
__device__ float g_wT[6][512][1024];          // ~12.6 MB

__device__ __forceinline__ float tanh_ap(float x) {
    float y; asm("tanh.approx.f32 %0, %1;" : "=f"(y) : "f"(x)); return y;
}
__device__ __forceinline__ float sigm_ap(float x) {
    return 0.5f * tanh_ap(0.5f * x) + 0.5f;
}
__device__ __forceinline__ float to_tf32(float x) {
    float r; asm("cvt.rna.tf32.f32 %0, %1;" : "=f"(r) : "f"(x)); return r;
}
__device__ __forceinline__ uint32_t pack_bf16x2(float x, float y) {
    __nv_bfloat162 p = __floats2bfloat162_rn(x, y);
    return *(uint32_t*)&p;
}
__device__ __forceinline__ uint32_t smem_u32(const void* p) {
    return (uint32_t)__cvta_generic_to_shared(p);
}
__device__ __forceinline__ uint32_t mapa_rank(uint32_t a, uint32_t r) {
    uint32_t d;
    asm("mapa.shared::cluster.u32 %0, %1, %2;" : "=r"(d) : "r"(a), "r"(r));
    return d;
}
__device__ __forceinline__ void st_cluster_f32(uint32_t a, float v) {
    asm volatile("st.shared::cluster.f32 [%0], %1;" :: "r"(a), "f"(v) : "memory");
}
__device__ __forceinline__ void mbar_init(uint32_t a, uint32_t cnt) {
    asm volatile("mbarrier.init.shared.b64 [%0], %1;" :: "r"(a), "r"(cnt) : "memory");
}
__device__ __forceinline__ void mbar_arrive_cluster(uint32_t a) {
    asm volatile("mbarrier.arrive.release.cluster.shared::cluster.b64 _, [%0];"
                 :: "r"(a) : "memory");
}
__device__ __forceinline__ void mbar_wait_acq(uint32_t a, uint32_t par) {
    uint32_t done;
    asm volatile(
        "{\n\t.reg .pred p;\n\t"
        "mbarrier.try_wait.parity.acquire.cluster.shared::cta.b64 p, [%1], %2;\n\t"
        "selp.b32 %0, 1, 0, p;\n\t}"
        : "=r"(done) : "r"(a), "r"(par) : "memory");
    if (!done) {
        asm volatile(
            "{\n\t.reg .pred P1;\n\t"
            "WL_%=:\n\t"
            "mbarrier.try_wait.parity.acquire.cluster.shared::cta.b64 P1, [%0], %1, 0x989680;\n\t"
            "@P1 bra.uni WD_%=;\n\t"
            "bra.uni WL_%=;\n\t"
            "WD_%=:\n\t}"
            :: "r"(a), "r"(par) : "memory");
    }
}
__device__ __forceinline__ void cluster_sync_() {
    asm volatile("barrier.cluster.arrive.aligned;" ::: "memory");
    asm volatile("barrier.cluster.wait.aligned;" ::: "memory");
}
__device__ __forceinline__ void cp16(void* dst, const void* src) {
    asm volatile("cp.async.cg.shared.global [%0], [%1], 16;"
                 :: "r"(smem_u32(dst)), "l"(src) : "memory");
}
__device__ __forceinline__ void cp4(void* dst, const void* src) {
    asm volatile("cp.async.ca.shared.global [%0], [%1], 4;"
                 :: "r"(smem_u32(dst)), "l"(src) : "memory");
}
__device__ __forceinline__ void cp_commit() {
    asm volatile("cp.async.commit_group;" ::: "memory");
}
__device__ __forceinline__ void mma_tf32(float* d, const uint32_t* a,
                                         uint32_t b0, uint32_t b1) {
    asm volatile(
        "mma.sync.aligned.m16n8k8.row.col.f32.tf32.tf32.f32 "
        "{%0,%1,%2,%3}, {%4,%5,%6,%7}, {%8,%9}, {%0,%1,%2,%3};"
        : "+f"(d[0]), "+f"(d[1]), "+f"(d[2]), "+f"(d[3])
        : "r"(a[0]), "r"(a[1]), "r"(a[2]), "r"(a[3]), "r"(b0), "r"(b1));
}
__device__ __forceinline__ void mma_bf16(float* d, const uint32_t* a,
                                         uint32_t b0, uint32_t b1) {
    asm volatile(
        "mma.sync.aligned.m16n8k16.row.col.f32.bf16.bf16.f32 "
        "{%0,%1,%2,%3}, {%4,%5,%6,%7}, {%8,%9}, {%0,%1,%2,%3};"
        : "+f"(d[0]), "+f"(d[1]), "+f"(d[2]), "+f"(d[3])
        : "r"(a[0]), "r"(a[1]), "r"(a[2]), "r"(a[3]), "r"(b0), "r"(b1));
}

// ------------------------- conv_w transpose (tf32-rounded) ------------------
__global__ void transpose_w_kernel(const float* __restrict__ conv_w) {
    __shared__ float tile[32][33];
    int jb = blockIdx.z, o0 = blockIdx.y * 32, k0 = blockIdx.x * 32;
    int tx = threadIdx.x, ty = threadIdx.y;   // (32, 8)
#pragma unroll
    for (int i = 0; i < 32; i += 8)
        tile[ty + i][tx] = conv_w[((size_t)jb * 1024 + o0 + ty + i) * 512 + k0 + tx];
    __syncthreads();
#pragma unroll
    for (int i = 0; i < 32; i += 8)
        g_wT[jb][k0 + ty + i][o0 + tx] = to_tf32(tile[tx][ty + i]);
}

// ------------------------- pad init (tf32-rounded) --------------------------
__global__ void init_pads_kernel(const float* __restrict__ hidden) {
    int idx = blockIdx.x * blockDim.x + threadIdx.x;   // 32768
    if (idx >= 4 * 32 * 256) return;
    int lv = idx >> 13;
    int b  = (idx >> 8) & 31;
    int c  = idx & 255;
    g_xbuf[lv][b][c][0] = to_tf32(hidden[((size_t)((lv * 32 + b) * 256 + c)) * 2 + 1]);
}

// ------------------------- embedding GEMM ----------------------------------
// Writes tf32-rounded x0 to g_xbuf; exact fp32 tail (w=510,511) to out.
__global__ void __launch_bounds__(256, 2)
emb_gemm_kernel(const float* __restrict__ input,
                const float* __restrict__ emb_w,
                const float* __restrict__ emb_b,
                float* __restrict__ out) {
    __shared__ float As[16][132];
    __shared__ float Bs[16][136];
    const int o0 = blockIdx.x * 128, w0 = blockIdx.y * 128, b = blockIdx.z;
    const int tid = threadIdx.x, tx = tid & 15, ty = tid >> 4;

    float acc[8][8];
#pragma unroll
    for (int j = 0; j < 8; j++)
#pragma unroll
        for (int i = 0; i < 8; i++) acc[j][i] = 0.f;

    for (int k0 = 0; k0 < 128; k0 += 16) {
        __syncthreads();
        {
            int cg = tid & 3;
            int row = tid >> 2;
#pragma unroll
            for (int p = 0; p < 2; p++) {
                int r_ = row + p * 64;
                float4 v = *(const float4*)(emb_w + (size_t)(o0 + r_) * 128 + k0 + cg * 4);
                As[cg * 4 + 0][r_] = v.x; As[cg * 4 + 1][r_] = v.y;
                As[cg * 4 + 2][r_] = v.z; As[cg * 4 + 3][r_] = v.w;
            }
        }
        {
            for (int i = tid; i < 512; i += 256) {
                int r = i >> 5, q = i & 31;
                float4 v = *(const float4*)(input + (size_t)(b * 128 + k0 + r) * 512 + w0 + q * 4);
                Bs[r][q * 4 + 0] = v.x; Bs[r][q * 4 + 1] = v.y;
                Bs[r][q * 4 + 2] = v.z; Bs[r][q * 4 + 3] = v.w;
            }
        }
        __syncthreads();
#pragma unroll
        for (int k = 0; k < 16; k++) {
            float4 a0 = *(const float4*)&As[k][ty * 8];
            float4 a1 = *(const float4*)&As[k][ty * 8 + 4];
            float4 b0 = *(const float4*)&Bs[k][tx * 4];
            float4 b1 = *(const float4*)&Bs[k][64 + tx * 4];
            float av[8] = {a0.x, a0.y, a0.z, a0.w, a1.x, a1.y, a1.z, a1.w};
            float bv[8] = {b0.x, b0.y, b0.z, b0.w, b1.x, b1.y, b1.z, b1.w};
#pragma unroll
            for (int j = 0; j < 8; j++)
#pragma unroll
                for (int i = 0; i < 8; i++) acc[j][i] = fmaf(av[i], bv[j], acc[j][i]);
        }
    }
#pragma unroll
    for (int i = 0; i < 8; i++) {
        int o = o0 + ty * 8 + i;
        float bias = emb_b[o];
        float* dst = &g_xbuf[0][b][o][1 + w0];
#pragma unroll
        for (int j = 0; j < 8; j++) {
            int wl = (j < 4) ? (tx * 4 + j) : (64 + tx * 4 + (j - 4));
            float v = acc[j][i] + bias;
            dst[wl] = to_tf32(v);
            int wg = w0 + wl;
            if (wg >= 510)
                out[((size_t)(b * 256 + o)) * 2 + (wg - 510)] = v;   // exact x0 tail
        }
    }
}

// ------------------------- conv contribution GEMM (tf32 tensor cores) ------
__global__ void __launch_bounds__(256, 2)
conv_mma_kernel(int jb, int jl, int lay, int accum, const float* __restrict__ conv_b) {
    __shared__ float As[2][16][136];   // weights: [kk][o]
    __shared__ float Bs[2][16][136];   // x:       [kk][w]
    const int o0 = blockIdx.x * 128, w0 = blockIdx.y * 128, b = blockIdx.z;
    const int tid = threadIdx.x;
    const int wid = tid >> 5, lane = tid & 31;
    const int warp_m = wid >> 2;       // w half: 0..1
    const int warp_n = wid & 3;        // o quarter: 0..3
    const int lr = lane >> 2, lc = lane & 3;
    const int total = 32;

    float acc[4][4][4];                // [mt][nt][frag]
#pragma unroll
    for (int mt = 0; mt < 4; mt++)
#pragma unroll
        for (int nt = 0; nt < 4; nt++)
#pragma unroll
            for (int f = 0; f < 4; f++) acc[mt][nt][f] = 0.f;

    auto load_tile = [&](int buf, int kt) {
        int kk0 = kt << 4;
        const float* WT = &g_wT[jb][kk0][0];
#pragma unroll
        for (int s = 0; s < 2; s++) {
            int idx = tid + s * 256;
            int row = idx >> 5, c4 = idx & 31;
            cp16(&As[buf][row][c4 * 4], WT + (size_t)row * 1024 + o0 + c4 * 4);
        }
        {
            int row = tid >> 4;
            int colb = (tid & 15) * 8;
            int kkg = kk0 + row;
            const float* src = &g_xbuf[jl][b][kkg >> 1][w0 + (kkg & 1) + colb];
            if ((kkg & 1) == 0) {
                cp16(&Bs[buf][row][colb], src);
                cp16(&Bs[buf][row][colb + 4], src + 4);
            } else {
#pragma unroll
                for (int q = 0; q < 8; q++) cp4(&Bs[buf][row][colb + q], src + q);
            }
        }
    };

    load_tile(0, 0); cp_commit();
    load_tile(1, 1); cp_commit();

    for (int kt = 0; kt < total; kt++) {
        if (kt + 1 < total) asm volatile("cp.async.wait_group 1;" ::: "memory");
        else                asm volatile("cp.async.wait_group 0;" ::: "memory");
        __syncthreads();
        int buf = kt & 1;
        const float (*Aw)[136] = As[buf];
        const float (*Bx)[136] = Bs[buf];
#pragma unroll
        for (int ks = 0; ks < 16; ks += 8) {
            uint32_t af[4][4];
#pragma unroll
            for (int mt = 0; mt < 4; mt++) {
                int wl = warp_m * 64 + mt * 16 + lr;
                af[mt][0] = __float_as_uint(Bx[ks + lc][wl]);
                af[mt][1] = __float_as_uint(Bx[ks + lc][wl + 8]);
                af[mt][2] = __float_as_uint(Bx[ks + 4 + lc][wl]);
                af[mt][3] = __float_as_uint(Bx[ks + 4 + lc][wl + 8]);
            }
#pragma unroll
            for (int nt = 0; nt < 4; nt++) {
                int ol = warp_n * 32 + nt * 8 + lr;
                uint32_t b0 = __float_as_uint(Aw[ks + lc][ol]);
                uint32_t b1 = __float_as_uint(Aw[ks + 4 + lc][ol]);
#pragma unroll
                for (int mt = 0; mt < 4; mt++)
                    mma_tf32(acc[mt][nt], af[mt], b0, b1);
            }
        }
        __syncthreads();
        if (kt + 2 < total) { load_tile(buf, kt + 2); cp_commit(); }
    }

#pragma unroll
    for (int mt = 0; mt < 4; mt++) {
        int wg = w0 + warp_m * 64 + mt * 16 + lr;
#pragma unroll
        for (int nt = 0; nt < 4; nt++) {
            int og = o0 + warp_n * 32 + nt * 8 + 2 * lc;
            float bi0 = conv_b[jb * 1024 + og];
            float bi1 = conv_b[jb * 1024 + og + 1];
            float* d0 = &g_ig[lay][b][wg][og];
            float* d1 = &g_ig[lay][b][wg + 8][og];
            float2 p0 = accum ? *(float2*)d0 : make_float2(0.f, 0.f);
            float2 p1 = accum ? *(float2*)d1 : make_float2(0.f, 0.f);
            float2 v0 = make_float2(p0.x + acc[mt][nt][0] + bi0,
                                    p0.y + acc[mt][nt][1] + bi1);
            float2 v1 = make_float2(p1.x + acc[mt][nt][2] + bi0,
                                    p1.y + acc[mt][nt][3] + bi1);
            *(float2*)d0 = v0;
            *(float2*)d1 = v1;
        }
    }
}

// ------------------------- LSTM scan (reg-resident bf16 mma, 4-CTA cluster)
// CTA rank r owns h in [64r, 64r+64). Gate row of matrix-row m:
//   G(m) = (m>>6)*256 + 64r + (m&63); thread t's row is m=t.
// Weights live in REGISTERS as mma.m16n8k16 A-fragments (128 regs/thread).
// Per step: wait f32 hr exchange -> attention partial reduce -> B-frag from
// hx (col 0 only) -> 32 warp-MMAs -> lanes l%4==0 finalize gq[m] ->
// local LSTM update (t<64) -> push f32 hr to 4 peers, warp-aggregated arrive.
__global__ void __launch_bounds__(256, 1) __cluster_dims__(4, 1, 1)
scan_kernel(int l,
            const float* __restrict__ hidden, const float* __restrict__ context,
            const float* __restrict__ rec_w, const float* __restrict__ rec_b,
            const float* __restrict__ attn_w, float* __restrict__ out) {
    __shared__ float hrbuf[2][256];
    __shared__ float gq[256];
    __shared__ float red[8];
    __shared__ uint64_t mbars[2];

    const int t = threadIdx.x;
    const int b = blockIdx.x >> 2;
    const int wid = t >> 5, lane = t & 31;
    uint32_t rank;
    asm("mov.u32 %0, %%cluster_ctarank;" : "=r"(rank));
    const int nl = l + 1;

    // ---- preload A-fragments (weights) into registers ----
    const float* rwl = rec_w + (size_t)l * 1024 * 256;
    const int gl = lane >> 2, kp = (lane & 3) * 2;
    uint32_t Af[2][16][4];
#pragma unroll
    for (int mt = 0; mt < 2; mt++) {
        int m0 = 32 * wid + 16 * mt + gl;
        int m1 = m0 + 8;
        int G0 = ((m0 >> 6) << 8) + 64 * (int)rank + (m0 & 63);
        int G1 = ((m1 >> 6) << 8) + 64 * (int)rank + (m1 & 63);
        const float* r0 = rwl + (size_t)G0 * 256 + kp;
        const float* r1 = rwl + (size_t)G1 * 256 + kp;
#pragma unroll
        for (int ks = 0; ks < 16; ks++) {
            Af[mt][ks][0] = pack_bf16x2(r0[ks * 16],     r0[ks * 16 + 1]);
            Af[mt][ks][1] = pack_bf16x2(r1[ks * 16],     r1[ks * 16 + 1]);
            Af[mt][ks][2] = pack_bf16x2(r0[ks * 16 + 8], r0[ks * 16 + 9]);
            Af[mt][ks][3] = pack_bf16x2(r1[ks * 16 + 8], r1[ks * 16 + 9]);
        }
    }
    // gate rows + rb for the finalize lanes (lane%4==0); harmless elsewhere
    int Gx[2][2];
    float rbv[2][2];
#pragma unroll
    for (int mt = 0; mt < 2; mt++) {
        int m0 = 32 * wid + 16 * mt + gl;
        int m1 = m0 + 8;
        Gx[mt][0] = ((m0 >> 6) << 8) + 64 * (int)rank + (m0 & 63);
        Gx[mt][1] = ((m1 >> 6) << 8) + 64 * (int)rank + (m1 & 63);
        rbv[mt][0] = rec_b[l * 1024 + Gx[mt][0]];
        rbv[mt][1] = rec_b[l * 1024 + Gx[mt][1]];
    }

    // initial hx into buffer 1
    hrbuf[1][t] = hidden[((size_t)((nl * 32 + b) * 256 + t)) * 2 + 1];

    const int h_glob = 64 * (int)rank + (t & 63);
    float cx = (t < 64) ? context[((size_t)((l * 32 + b) * 256 + h_glob)) * 2 + 1] : 0.f;
    float hr_prev = 0.f;
    const float aw_t = attn_w[l * 256 + t];

    const uint32_t hr_base = smem_u32(&hrbuf[0][0]);
    const uint32_t mb_base = smem_u32(&mbars[0]);
    uint32_t hr_peer[4], mb_peer[4];
#pragma unroll
    for (int r = 0; r < 4; r++) {
        hr_peer[r] = mapa_rank(hr_base, r);
        mb_peer[r] = mapa_rank(mb_base, r);
    }
    if (t == 0) { mbar_init(mb_base, 8); mbar_init(mb_base + 8, 8); }
    __syncthreads();
    cluster_sync_();

    const float* igb = &g_ig[l][b][0][0];
    float* gx_next = &g_xbuf[nl][b][0][0];

    for (int w = 0; w < 512; w++) {
        // prefetch ig values for the finalize lanes (hidden under wait+mma)
        float igv[2][2];
        if ((lane & 3) == 0) {
#pragma unroll
            for (int mt = 0; mt < 2; mt++) {
                igv[mt][0] = igb[(size_t)w * 1024 + Gx[mt][0]];
                igv[mt][1] = igb[(size_t)w * 1024 + Gx[mt][1]];
            }
        }

        const int jprev = (w + 1) & 1;
        if (w > 0) mbar_wait_acq(mb_base + (uint32_t)(jprev << 3),
                                 (uint32_t)(((w - 1) >> 1) & 1));
        const float* hrp = hrbuf[jprev];

        // attention partial reduce (result consumed after the sync below)
        float p = hrp[t] * aw_t;
#pragma unroll
        for (int o_ = 16; o_ > 0; o_ >>= 1) p += __shfl_xor_sync(0xffffffffu, p, o_);
        if (lane == 0) red[wid] = p;

        // ---- matvec on tensor pipe: D[256x8] col0 = W * hx ----
        float d0[4] = {0.f, 0.f, 0.f, 0.f};
        float d1[4] = {0.f, 0.f, 0.f, 0.f};
#pragma unroll
        for (int ks = 0; ks < 16; ks++) {
            uint32_t b0 = 0, b1 = 0;
            if (lane < 4) {
                float2 x0 = *(const float2*)&hrp[ks * 16 + 2 * lane];
                float2 x1 = *(const float2*)&hrp[ks * 16 + 8 + 2 * lane];
                b0 = pack_bf16x2(x0.x, x0.y);
                b1 = pack_bf16x2(x1.x, x1.y);
            }
            mma_bf16(d0, Af[0][ks], b0, b1);
            mma_bf16(d1, Af[1][ks], b0, b1);
        }
        __syncthreads();   // red visible; prior-step gq reads complete

        float s = 0.f;
#pragma unroll
        for (int q = 0; q < 8; q++) s += red[q];
        float a_prev = (w > 0) ? sigm_ap(s) : 1.f;

        if ((lane & 3) == 0) {
            int mbase = 32 * wid + gl;
            gq[mbase]          = a_prev * d0[0] + rbv[0][0] + igv[0][0];
            gq[mbase + 8]      = a_prev * d0[2] + rbv[0][1] + igv[0][1];
            gq[mbase + 16]     = a_prev * d1[0] + rbv[1][0] + igv[1][0];
            gq[mbase + 24]     = a_prev * d1[2] + rbv[1][1] + igv[1][1];
        }
        __syncthreads();   // gq visible

        if (t < 64) {
            if (w > 0) {
                float hxprev = hr_prev * a_prev;
                gx_next[(size_t)h_glob * XW + w] = to_tf32(hxprev);
                if (w == 511)
                    out[((size_t)((nl * 32 + b) * 256 + h_glob)) * 2 + 0] = hxprev;
            }
            float gi = gq[t], gf = gq[64 + t], gc = gq[128 + t], go = gq[192 + t];
            cx = sigm_ap(gf) * cx + sigm_ap(gi) * tanh_ap(gc);
            float hr = sigm_ap(go) * tanh_ap(cx);
            if (w >= 510)
                out[NC_OFF + ((size_t)((l * 32 + b) * 256 + h_glob)) * 2 + (w - 510)] = cx;
            if (w == 511) {
                out[((size_t)((nl * 32 + b) * 256 + h_glob)) * 2 + 1] = hr;
                gx_next[(size_t)h_glob * XW + 512] = to_tf32(hr);
            } else {
                uint32_t soff = (uint32_t)(((w & 1) << 10) + (h_glob << 2));
#pragma unroll
                for (int r = 0; r < 4; r++) st_cluster_f32(hr_peer[r] + soff, hr);
                __syncwarp();
                if (lane == 0) {   // warp-aggregated release-arrive (8 per mbar)
#pragma unroll
                    for (int r = 0; r < 4; r++)
                        mbar_arrive_cluster(mb_peer[r] + (uint32_t)((w & 1) << 3));
                }
            }
            hr_prev = hr;
        }
        if (rank == 0 && t == 0 && w > 0)
            out[ATTN_OFF + (size_t)(l * 32 + b) * 511 + (w - 1)] = a_prev;
    }
    cluster_sync_();   // keep smem alive for in-flight peer stores
}

// ---------------------------------------------------------------------------
extern "C" void kernel_launch(void* const* d_in, const int* in_sizes, int n_in,
                              void* d_out, int out_size) {
    const float* input   = (const float*)d_in[0];
    const float* hidden  = (const float*)d_in[1];
    const float* context = (const float*)d_in[2];
    const float* emb_w   = (const float*)d_in[3];
    const float* emb_b   = (const float*)d_in[4];
    const float* conv_w  = (const float*)d_in[5];
    const float* conv_b  = (const float*)d_in[6];
    const float* rec_w   = (const float*)d_in[7];
    const float* rec_b   = (const float*)d_in[8];
    const float* attn_w  = (const float*)d_in[9];
    float* out = (float*)d_out;

    const dim3 cgrid(8, 4, 32);

    transpose_w_kernel<<<dim3(16, 32, 6), dim3(32, 8)>>>(conv_w);
    init_pads_kernel<<<128, 256>>>(hidden);
    emb_gemm_kernel<<<dim3(2, 4, 32), 256>>>(input, emb_w, emb_b, out);

    for (int l = 0; l < 3; l++) {
        int off = (l * (l + 1)) >> 1;
        for (int j = 0; j <= l; j++)
            conv_mma_kernel<<<cgrid, 256>>>(off + j, j, l, j > 0, conv_b);
        scan_kernel<<<128, 256>>>(l, hidden, context, rec_w, rec_b, attn_w, out);
    }
}